// round 2
// baseline (speedup 1.0000x reference)
#include <cuda_runtime.h>

// FINN DiffSorp: 1-D diffusion-sorption, RK4, 63 steps, NX=262144, 2 channels.
// Single-launch strategy: channel-0 stencil radius is 1 per stage -> 252 total.
// Each block owns TILE=1800 interior points with HALO=252 on each side (arena
// 2304 = 576 threads * 4 points). All 63 RK4 steps run in shared memory; the
// only global traffic is the initial state read and the mandatory output
// writes. Arena-edge garbage propagates 1 point/stage and never reaches the
// interior (distance 252, stages 252, first-wrong at stage 1 => reach <= 251).
// Global boundaries (g==0, g==NX-1) use the exact reference BC formulas.

#define NXC      262144
#define TSTEPS   64
#define THREADS  576
#define PPT      4
#define ARENA    (THREADS * PPT)        // 2304
#define HALO     252                    // 4 stages/step * 63 steps
#define TILE     (ARENA - 2 * HALO)     // 1800
#define NBLOCKS  ((NXC + TILE - 1) / TILE)  // 146

struct Uni {
    float D0, D1, BC00, s1, ts0, D0dx, w0, w1, w2, w3;
};

// One stage evaluation at arena index a (global index g) reading stage state S.
// Returns c = S[a], tot (shared by both channels), flux = D0/ret * tot.
__device__ __forceinline__ void stage_eval(const float* __restrict__ S, int a, int g,
                                           const Uni& U, float& c, float& flux, float& tot)
{
    c = S[a];
    float cm = (a > 0) ? S[a - 1] : c;            // artificial edge: garbage OK
    if (g == 0) cm = U.BC00;                      // left Dirichlet BC
    float cp = (a < ARENA - 1) ? S[a + 1] : c;    // artificial edge: garbage OK
    if (g == NXC - 1) cp = U.D0dx * (S[a - 1] - c); // right BC term
    tot = fmaf(U.ts0, c, U.s1 * (cm + cp));       // 2*s0*c + s1*(cm+cp)
    float ret = fabsf(fmaf(fmaf(fmaf(U.w3, c, U.w2), c, U.w1), c, U.w0)); // |poly(c)|
    flux = __fdividef(U.D0 * tot, ret);
}

__global__ __launch_bounds__(THREADS, 1)
void diffsorp_kernel(const float* __restrict__ tarr,
                     const float* __restrict__ u,
                     const float* __restrict__ Din,
                     const float* __restrict__ BCin,
                     const float* __restrict__ stin,
                     const float* __restrict__ cfin,
                     const float* __restrict__ dxin,
                     float* __restrict__ out)
{
    __shared__ float SA[ARENA];   // current step base state (channel 0)
    __shared__ float SB[ARENA];   // stage ping buffer
    __shared__ float SC[ARENA];   // stage pong buffer
    __shared__ float st[TSTEPS];  // time points

    const int tid = threadIdx.x;
    const long long base_g = (long long)blockIdx.x * TILE - HALO;

    Uni U;
    U.D0   = __ldg(Din);
    U.D1   = __ldg(Din + 1);
    U.BC00 = __ldg(BCin);                 // BC[0,0]
    float s0 = __ldg(stin);
    U.s1   = __ldg(stin + 1);
    U.ts0  = 2.0f * s0;
    U.D0dx = U.D0 * __ldg(dxin);
    U.w0 = __ldg(cfin);     U.w1 = __ldg(cfin + 1);
    U.w2 = __ldg(cfin + 2); U.w3 = __ldg(cfin + 3);

    if (tid < TSTEPS) st[tid] = tarr[tid];

    float ctv[PPT];     // channel-1 state (per owned point, interior only matters)
    float cbase[PPT];   // channel-0 base state for the current RK4 step
    int   ga[PPT];
    bool  inter[PPT];

    // Initial load + t=0 output slice
    #pragma unroll
    for (int k = 0; k < PPT; k++) {
        int a = tid + k * THREADS;
        long long g = base_g + a;
        ga[k] = (int)g;
        bool valid = (g >= 0 && g < NXC);
        inter[k] = (a >= HALO) && (a < HALO + TILE) && (g < NXC);
        float c = 0.0f, ct = 0.0f;
        if (valid) {
            float2 v = *(const float2*)(u + 2 * g);
            c = v.x; ct = v.y;
        }
        SA[a] = c;
        ctv[k] = ct;
        if (inter[k])
            *(float2*)(out + 2 * (size_t)ga[k]) = make_float2(c, ct);
    }
    __syncthreads();

    for (int m = 1; m < TSTEPS; m++) {
        const float dt  = st[m] - st[m - 1];
        const float hdt = 0.5f * dt;
        float kacc[PPT], acc[PPT];

        // Stage 1: reads SA (base state)
        #pragma unroll
        for (int k = 0; k < PPT; k++) {
            int a = tid + k * THREADS;
            float c, fl, tt;
            stage_eval(SA, a, ga[k], U, c, fl, tt);
            cbase[k] = c;
            kacc[k] = fl;
            acc[k]  = tt;
            SB[a] = fmaf(hdt, fl, c);
        }
        __syncthreads();

        // Stage 2: reads SB
        #pragma unroll
        for (int k = 0; k < PPT; k++) {
            int a = tid + k * THREADS;
            float c, fl, tt;
            stage_eval(SB, a, ga[k], U, c, fl, tt);
            kacc[k] = fmaf(2.0f, fl, kacc[k]);
            acc[k]  = fmaf(2.0f, tt, acc[k]);
            SC[a] = fmaf(hdt, fl, cbase[k]);
        }
        __syncthreads();

        // Stage 3: reads SC
        #pragma unroll
        for (int k = 0; k < PPT; k++) {
            int a = tid + k * THREADS;
            float c, fl, tt;
            stage_eval(SC, a, ga[k], U, c, fl, tt);
            kacc[k] = fmaf(2.0f, fl, kacc[k]);
            acc[k]  = fmaf(2.0f, tt, acc[k]);
            SB[a] = fmaf(dt, fl, cbase[k]);
        }
        __syncthreads();

        // Stage 4: reads SB, final combine, write output slice m
        float* orow = out + (size_t)m * (NXC * 2);
        #pragma unroll
        for (int k = 0; k < PPT; k++) {
            int a = tid + k * THREADS;
            float c, fl, tt;
            stage_eval(SB, a, ga[k], U, c, fl, tt);
            kacc[k] += fl;
            acc[k]  += tt;
            const float w = dt * (1.0f / 6.0f);
            float cn  = fmaf(w, kacc[k], cbase[k]);
            float ctn = fmaf(w * U.D1, acc[k], ctv[k]);
            SA[a] = cn;
            ctv[k] = ctn;
            if (inter[k])
                *(float2*)(orow + 2 * (size_t)ga[k]) = make_float2(cn, ctn);
        }
        __syncthreads();
    }
}

extern "C" void kernel_launch(void* const* d_in, const int* in_sizes, int n_in,
                              void* d_out, int out_size)
{
    (void)in_sizes; (void)n_in; (void)out_size;
    diffsorp_kernel<<<NBLOCKS, THREADS>>>(
        (const float*)d_in[0],   // t
        (const float*)d_in[1],   // u
        (const float*)d_in[2],   // D
        (const float*)d_in[3],   // BC
        (const float*)d_in[4],   // stencil
        (const float*)d_in[5],   // coeffs
        (const float*)d_in[6],   // dx
        (float*)d_out);
}

// round 3
// speedup vs baseline: 1.1715x; 1.1715x over previous
#include <cuda_runtime.h>

// FINN DiffSorp: 1-D diffusion-sorption, RK4, 63 steps, NX=262144, 2 channels.
// Single launch; all 63 RK4 steps (252 stencil stages) computed per block with
// HALO=252 recompute halo. R2: state lives in REGISTERS (4 contiguous points
// per thread); per stage only the two thread-boundary values are exchanged via
// double-buffered shared arrays (2 LDS + 2 STS per thread per stage, one
// __syncthreads per stage). HALO = 63 threads * 4, so interiority is a
// per-thread constant and output rows are two float4 stores.
//
// Contamination: arena-edge garbage advances 1 point/stage; after 252 stages
// it reaches arena index 251 < 252 (first interior). Global BCs (g==0 Dirichlet
// via SEL, g==NX-1 Robin via SEL) are applied every stage, so edge blocks are
// exact. (R1 validated this construction: rel_err 3.4e-9.)

#define NXC      262144
#define TSTEPS   64
#define THREADS  576
#define PPT      4
#define ARENA    (THREADS * PPT)        // 2304
#define HALO     252
#define TILE     (ARENA - 2 * HALO)     // 1800
#define NBLOCKS  ((NXC + TILE - 1) / TILE)  // 146

struct Uni {
    float BC00, s1, ts0, D0dx, w0, w1, w2, w3, D0, D1;
};

// Evaluate one stencil stage on 4 register-resident points.
// tot[k] = 2*s0*c + s1*(cm+cp);  q[k] = tot/|poly(c)|   (D0 factored out).
__device__ __forceinline__ void eval4(const float* __restrict__ s,
                                      float cmL, float cpR, const Uni& U,
                                      bool bcL, bool bcR,
                                      float* __restrict__ tot,
                                      float* __restrict__ q)
{
    const float cm0 = bcL ? U.BC00 : cmL;
    const float cpr = bcR ? U.D0dx * (s[2] - s[3]) : cpR;
    #pragma unroll
    for (int k = 0; k < 4; k++) {
        const float cm = (k == 0) ? cm0 : s[k - 1];
        const float cp = (k == 3) ? cpr : s[k + 1];
        const float c  = s[k];
        const float t  = fmaf(U.ts0, c, U.s1 * (cm + cp));
        const float r  = fabsf(fmaf(fmaf(fmaf(U.w3, c, U.w2), c, U.w1), c, U.w0));
        tot[k] = t;
        q[k]   = __fdividef(t, r);
    }
}

__global__ __launch_bounds__(THREADS, 1)
void diffsorp_kernel(const float* __restrict__ tarr,
                     const float* __restrict__ u,
                     const float* __restrict__ Din,
                     const float* __restrict__ BCin,
                     const float* __restrict__ stin,
                     const float* __restrict__ cfin,
                     const float* __restrict__ dxin,
                     float* __restrict__ out)
{
    // Edge exchange buffers, double-buffered; index tid+1, slots 0 and
    // THREADS+1 are permanent-garbage padding (read only by arena-edge halo).
    __shared__ float Lb[2][THREADS + 2];
    __shared__ float Rb[2][THREADS + 2];
    __shared__ float st[TSTEPS];

    const int tid = threadIdx.x;
    const long long g0l = (long long)blockIdx.x * TILE - HALO + PPT * (long long)tid;

    Uni U;
    U.BC00 = __ldg(BCin);
    const float s0 = __ldg(stin);
    U.s1   = __ldg(stin + 1);
    U.ts0  = 2.0f * s0;
    U.D0   = __ldg(Din);
    U.D1   = __ldg(Din + 1);
    U.D0dx = U.D0 * __ldg(dxin);
    U.w0 = __ldg(cfin);     U.w1 = __ldg(cfin + 1);
    U.w2 = __ldg(cfin + 2); U.w3 = __ldg(cfin + 3);

    if (tid < TSTEPS) st[tid] = tarr[tid];

    const bool inter = (tid >= HALO / PPT) && (tid < (HALO + TILE) / PPT); // [63,513)
    const bool bcL   = (g0l == 0);
    const bool bcR   = (g0l + 3 == NXC - 1);
    const bool allv  = (g0l >= 0) && (g0l + 3 < NXC);

    float c[PPT], ctv[PPT];

    // ── Initial load ─────────────────────────────────────────────────────
    if (allv) {
        const float4 v0 = *(const float4*)(u + 2 * g0l);
        const float4 v1 = *(const float4*)(u + 2 * g0l + 4);
        c[0] = v0.x; ctv[0] = v0.y; c[1] = v0.z; ctv[1] = v0.w;
        c[2] = v1.x; ctv[2] = v1.y; c[3] = v1.z; ctv[3] = v1.w;
    } else {
        #pragma unroll
        for (int k = 0; k < PPT; k++) {
            const long long g = g0l + k;
            if (g >= 0 && g < NXC) {
                const float2 v = *(const float2*)(u + 2 * g);
                c[k] = v.x; ctv[k] = v.y;
            } else { c[k] = 0.0f; ctv[k] = 0.0f; }
        }
    }

    // ── t=0 output row ───────────────────────────────────────────────────
    if (inter) {
        float* o = out + 2 * (size_t)g0l;
        if (allv) {
            *(float4*)(o)     = make_float4(c[0], ctv[0], c[1], ctv[1]);
            *(float4*)(o + 4) = make_float4(c[2], ctv[2], c[3], ctv[3]);
        } else {
            #pragma unroll
            for (int k = 0; k < PPT; k++)
                if (g0l + k < NXC)
                    *(float2*)(o + 2 * k) = make_float2(c[k], ctv[k]);
        }
    }

    // Base-state edges -> buffer 0
    Lb[0][tid + 1] = c[0];
    Rb[0][tid + 1] = c[3];
    __syncthreads();

    // ── Time loop ────────────────────────────────────────────────────────
    for (int m = 1; m < TSTEPS; m++) {
        const float dt = st[m] - st[m - 1];
        const float hD = 0.5f * dt * U.D0;    // stage-2/3 input scale
        const float fD = dt * U.D0;           // stage-4 input scale
        const float wc = dt * (1.0f / 6.0f) * U.D0;
        const float wt = dt * (1.0f / 6.0f) * U.D1;

        float t1[PPT], q1[PPT], kq[PPT], at[PPT], sA[PPT], sB[PPT];

        // Stage 1: reads base c, edges buf0 -> writes edges buf1
        eval4(c, Rb[0][tid], Lb[0][tid + 2], U, bcL, bcR, t1, q1);
        #pragma unroll
        for (int k = 0; k < PPT; k++) {
            kq[k] = q1[k];
            at[k] = t1[k];
            sA[k] = fmaf(hD, q1[k], c[k]);
        }
        Lb[1][tid + 1] = sA[0];
        Rb[1][tid + 1] = sA[3];
        __syncthreads();

        // Stage 2: reads sA, edges buf1 -> writes edges buf0
        eval4(sA, Rb[1][tid], Lb[1][tid + 2], U, bcL, bcR, t1, q1);
        #pragma unroll
        for (int k = 0; k < PPT; k++) {
            kq[k] = fmaf(2.0f, q1[k], kq[k]);
            at[k] = fmaf(2.0f, t1[k], at[k]);
            sB[k] = fmaf(hD, q1[k], c[k]);
        }
        Lb[0][tid + 1] = sB[0];
        Rb[0][tid + 1] = sB[3];
        __syncthreads();

        // Stage 3: reads sB, edges buf0 -> writes edges buf1
        eval4(sB, Rb[0][tid], Lb[0][tid + 2], U, bcL, bcR, t1, q1);
        #pragma unroll
        for (int k = 0; k < PPT; k++) {
            kq[k] = fmaf(2.0f, q1[k], kq[k]);
            at[k] = fmaf(2.0f, t1[k], at[k]);
            sA[k] = fmaf(fD, q1[k], c[k]);      // reuse sA as stage-4 state
        }
        Lb[1][tid + 1] = sA[0];
        Rb[1][tid + 1] = sA[3];
        __syncthreads();

        // Stage 4: reads sA, edges buf1 -> new base, writes edges buf0
        eval4(sA, Rb[1][tid], Lb[1][tid + 2], U, bcL, bcR, t1, q1);
        #pragma unroll
        for (int k = 0; k < PPT; k++) {
            kq[k] += q1[k];
            at[k] += t1[k];
            c[k]   = fmaf(wc, kq[k], c[k]);
            ctv[k] = fmaf(wt, at[k], ctv[k]);
        }
        Lb[0][tid + 1] = c[0];
        Rb[0][tid + 1] = c[3];
        __syncthreads();

        // Output row m (registers only; safe after barrier)
        if (inter) {
            float* o = out + (size_t)m * (NXC * 2) + 2 * (size_t)g0l;
            if (allv) {
                *(float4*)(o)     = make_float4(c[0], ctv[0], c[1], ctv[1]);
                *(float4*)(o + 4) = make_float4(c[2], ctv[2], c[3], ctv[3]);
            } else {
                #pragma unroll
                for (int k = 0; k < PPT; k++)
                    if (g0l + k < NXC)
                        *(float2*)(o + 2 * k) = make_float2(c[k], ctv[k]);
            }
        }
    }
}

extern "C" void kernel_launch(void* const* d_in, const int* in_sizes, int n_in,
                              void* d_out, int out_size)
{
    (void)in_sizes; (void)n_in; (void)out_size;
    diffsorp_kernel<<<NBLOCKS, THREADS>>>(
        (const float*)d_in[0],   // t
        (const float*)d_in[1],   // u
        (const float*)d_in[2],   // D
        (const float*)d_in[3],   // BC
        (const float*)d_in[4],   // stencil
        (const float*)d_in[5],   // coeffs
        (const float*)d_in[6],   // dx
        (float*)d_out);
}